// round 2
// baseline (speedup 1.0000x reference)
#include <cuda_runtime.h>
#include <cstdint>

// Problem constants (fixed shapes from reference)
#define BATCH 32
#define HW    16384       // 128*128
#define NCLS  80
#define NPB   (HW * NCLS) // 1310720 scores per batch
#define KTOP  100
#define BINS  2048        // top-11 bits of monotonic key
#define CAP   4096        // candidate buffer per batch

// __device__ scratch (no allocation allowed)
__device__ unsigned int g_hist[BATCH][BINS];
__device__ int          g_cnt[BATCH];
__device__ int          g_cut[BATCH];
__device__ uint2        g_cand[BATCH][CAP];   // (key, linear index)

// Order-preserving float->uint mapping (descending float == descending key)
__device__ __forceinline__ unsigned int f2key(float f) {
    unsigned int u = __float_as_uint(f);
    return (u & 0x80000000u) ? ~u : (u | 0x80000000u);
}
__device__ __forceinline__ float key2f(unsigned int k) {
    unsigned int u = (k & 0x80000000u) ? (k ^ 0x80000000u) : ~k;
    return __uint_as_float(u);
}

// ---------------------------------------------------------------------------
// Pass 0: zero scratch
__global__ void zero_kernel() {
    int total = BATCH * BINS;
    for (int i = blockIdx.x * blockDim.x + threadIdx.x; i < total;
         i += gridDim.x * blockDim.x)
        ((unsigned int*)g_hist)[i] = 0;
    if (blockIdx.x == 0 && threadIdx.x < BATCH) g_cnt[threadIdx.x] = 0;
}

// ---------------------------------------------------------------------------
// Pass 1: per-batch histogram of key>>21 with warp-aggregated atomics
__global__ void hist_kernel(const float* __restrict__ cls) {
    __shared__ unsigned int sh[BINS];
    const int b = blockIdx.y;
    for (int i = threadIdx.x; i < BINS; i += blockDim.x) sh[i] = 0;
    __syncthreads();

    const float4* p = (const float4*)(cls + (size_t)b * NPB);
    const int n4 = NPB / 4;
    const int stride = gridDim.x * blockDim.x;
    const int lane = threadIdx.x & 31;

    for (int i = blockIdx.x * blockDim.x + threadIdx.x; i < n4; i += stride) {
        float4 v = p[i];
        unsigned int k0 = f2key(v.x) >> 21;
        unsigned int k1 = f2key(v.y) >> 21;
        unsigned int k2 = f2key(v.z) >> 21;
        unsigned int k3 = f2key(v.w) >> 21;
        #pragma unroll
        for (int j = 0; j < 4; j++) {
            unsigned int bin = (j == 0) ? k0 : (j == 1) ? k1 : (j == 2) ? k2 : k3;
            // aggregate equal-bin lanes within the warp: 1 atomic per distinct bin
            unsigned int mask = __match_any_sync(0xffffffffu, bin);
            int leader = __ffs(mask) - 1;
            if (lane == leader) atomicAdd(&sh[bin], (unsigned int)__popc(mask));
        }
    }
    __syncthreads();
    for (int i = threadIdx.x; i < BINS; i += blockDim.x)
        if (sh[i]) atomicAdd(&g_hist[b][i], sh[i]);
}

// ---------------------------------------------------------------------------
// Pass 2: find cutoff bin (first bin from the top where cumulative >= K)
__global__ void cut_kernel() {
    int b = blockIdx.x;
    if (threadIdx.x == 0) {
        unsigned int s = 0;
        int cut = 0;
        for (int i = BINS - 1; i >= 0; i--) {
            s += g_hist[b][i];
            if (s >= KTOP) { cut = i; break; }
        }
        g_cut[b] = cut;
    }
}

// ---------------------------------------------------------------------------
// Pass 3: collect candidates in bins >= cutoff
__global__ void collect_kernel(const float* __restrict__ cls) {
    const int b = blockIdx.y;
    const unsigned int cut = (unsigned int)g_cut[b];
    const float4* p = (const float4*)(cls + (size_t)b * NPB);
    const int n4 = NPB / 4;
    const int stride = gridDim.x * blockDim.x;

    for (int i = blockIdx.x * blockDim.x + threadIdx.x; i < n4; i += stride) {
        float4 v = p[i];
        unsigned int ks[4] = { f2key(v.x), f2key(v.y), f2key(v.z), f2key(v.w) };
        #pragma unroll
        for (int j = 0; j < 4; j++) {
            if ((ks[j] >> 21) >= cut) {
                int pos = atomicAdd(&g_cnt[b], 1);
                if (pos < CAP)
                    g_cand[b][pos] = make_uint2(ks[j], (unsigned int)(4 * i + j));
            }
        }
    }
}

// ---------------------------------------------------------------------------
// Pass 4: exact rank among candidates (key desc, index asc tie-break = jax
// top_k semantics), gather boxes, write [B, K, 6] output.
__global__ void select_kernel(const float* __restrict__ loc,
                              float* __restrict__ out) {
    __shared__ uint2 cand[CAP];
    const int b = blockIdx.x;
    const int n = min(g_cnt[b], CAP);
    for (int i = threadIdx.x; i < n; i += blockDim.x) cand[i] = g_cand[b][i];
    __syncthreads();

    for (int i = threadIdx.x; i < n; i += blockDim.x) {
        const unsigned int ki = cand[i].x;
        const unsigned int xi = cand[i].y;
        int rank = 0;
        for (int j = 0; j < n; j++) {
            unsigned int kj = cand[j].x;
            unsigned int xj = cand[j].y;
            rank += (kj > ki) || (kj == ki && xj < xi);
        }
        if (rank < KTOP) {
            unsigned int cls_id = xi % NCLS;
            unsigned int sp = xi / NCLS;
            float4 box = ((const float4*)(loc + (size_t)b * HW * 4))[sp];
            float* o = out + ((size_t)b * KTOP + rank) * 6;
            o[0] = box.x; o[1] = box.y; o[2] = box.z; o[3] = box.w;
            o[4] = key2f(ki);
            o[5] = (float)cls_id;
        }
    }
}

// ---------------------------------------------------------------------------
extern "C" void kernel_launch(void* const* d_in, const int* in_sizes, int n_in,
                              void* d_out, int out_size) {
    // cls_pred has 32*128*128*80 = 41943040 elems; loc_pred 32*128*128*4 = 2097152
    const float* cls = (const float*)d_in[0];
    const float* loc = (const float*)d_in[1];
    if (n_in >= 2 && in_sizes[0] < in_sizes[1]) {
        cls = (const float*)d_in[1];
        loc = (const float*)d_in[0];
    }
    float* out = (float*)d_out;

    zero_kernel<<<64, 256>>>();
    hist_kernel<<<dim3(128, BATCH), 256>>>(cls);
    cut_kernel<<<BATCH, 32>>>();
    collect_kernel<<<dim3(128, BATCH), 256>>>(cls);
    select_kernel<<<BATCH, 256>>>(loc, out);
}

// round 3
// speedup vs baseline: 1.1066x; 1.1066x over previous
#include <cuda_runtime.h>
#include <cstdint>

// Problem constants (fixed shapes from reference)
#define BATCH 32
#define HW    16384       // 128*128
#define NCLS  80
#define NPB   (HW * NCLS) // 1310720 scores per batch
#define KTOP  100
#define BINS  2048        // top-11 bits of monotonic key
#define CAP   4096        // candidate buffer per batch

// __device__ scratch (no allocation allowed)
__device__ unsigned int g_hist[BATCH][BINS];
__device__ int          g_cnt[BATCH];
__device__ int          g_cut[BATCH];
__device__ uint2        g_cand[BATCH][CAP];   // (key, linear index)

// Order-preserving float->uint mapping (descending float == descending key)
__device__ __forceinline__ unsigned int f2key(float f) {
    unsigned int u = __float_as_uint(f);
    return (u & 0x80000000u) ? ~u : (u | 0x80000000u);
}
__device__ __forceinline__ float key2f(unsigned int k) {
    unsigned int u = (k & 0x80000000u) ? (k ^ 0x80000000u) : ~k;
    return __uint_as_float(u);
}

// ---------------------------------------------------------------------------
// Pass 0: zero scratch
__global__ void zero_kernel() {
    int total = BATCH * BINS;
    for (int i = blockIdx.x * blockDim.x + threadIdx.x; i < total;
         i += gridDim.x * blockDim.x)
        ((unsigned int*)g_hist)[i] = 0;
    if (blockIdx.x == 0 && threadIdx.x < BATCH) g_cnt[threadIdx.x] = 0;
}

// ---------------------------------------------------------------------------
// Pass 1: per-batch histogram of key>>21 with warp-aggregated atomics
__global__ void hist_kernel(const float* __restrict__ cls) {
    __shared__ unsigned int sh[BINS];
    const int b = blockIdx.y;
    for (int i = threadIdx.x; i < BINS; i += blockDim.x) sh[i] = 0;
    __syncthreads();

    const float4* p = (const float4*)(cls + (size_t)b * NPB);
    const int n4 = NPB / 4;
    const int stride = gridDim.x * blockDim.x;
    const int lane = threadIdx.x & 31;

    for (int i = blockIdx.x * blockDim.x + threadIdx.x; i < n4; i += stride) {
        float4 v = p[i];
        unsigned int k0 = f2key(v.x) >> 21;
        unsigned int k1 = f2key(v.y) >> 21;
        unsigned int k2 = f2key(v.z) >> 21;
        unsigned int k3 = f2key(v.w) >> 21;
        #pragma unroll
        for (int j = 0; j < 4; j++) {
            unsigned int bin = (j == 0) ? k0 : (j == 1) ? k1 : (j == 2) ? k2 : k3;
            // aggregate equal-bin lanes within the warp: 1 atomic per distinct bin
            unsigned int mask = __match_any_sync(0xffffffffu, bin);
            int leader = __ffs(mask) - 1;
            if (lane == leader) atomicAdd(&sh[bin], (unsigned int)__popc(mask));
        }
    }
    __syncthreads();
    for (int i = threadIdx.x; i < BINS; i += blockDim.x)
        if (sh[i]) atomicAdd(&g_hist[b][i], sh[i]);
}

// ---------------------------------------------------------------------------
// Pass 2: find cutoff bin (first bin from the top where cumulative >= K).
// Parallel version: coalesced load of all bins into shared, chunked suffix
// scan. One 256-thread block per batch.
#define CUT_THREADS 256
#define CHUNK (BINS / CUT_THREADS)   // 8 bins per thread
__global__ void cut_kernel() {
    __shared__ unsigned int sb[BINS];
    __shared__ unsigned int csum[CUT_THREADS];
    __shared__ int s_cut;
    const int b = blockIdx.x;
    const int t = threadIdx.x;

    // coalesced load of the whole histogram
    #pragma unroll
    for (int i = 0; i < CHUNK; i++)
        sb[t + i * CUT_THREADS] = g_hist[b][t + i * CUT_THREADS];
    __syncthreads();

    // each thread sums its contiguous chunk [t*CHUNK, t*CHUNK+CHUNK)
    unsigned int s = 0;
    #pragma unroll
    for (int i = 0; i < CHUNK; i++) s += sb[t * CHUNK + i];
    csum[t] = s;
    __syncthreads();

    // thread 0: suffix-scan chunk sums from the top, then resolve within chunk
    if (t == 0) {
        unsigned int acc = 0;
        int cut = 0;
        for (int c = CUT_THREADS - 1; c >= 0; c--) {
            unsigned int ns = acc + csum[c];
            if (ns >= KTOP) {
                // crossing is inside chunk c: walk its 8 bins from the top
                for (int i = CHUNK - 1; i >= 0; i--) {
                    acc += sb[c * CHUNK + i];
                    if (acc >= KTOP) { cut = c * CHUNK + i; break; }
                }
                break;
            }
            acc = ns;
        }
        s_cut = cut;
    }
    __syncthreads();
    if (t == 0) g_cut[b] = s_cut;
}

// ---------------------------------------------------------------------------
// Pass 3: collect candidates in bins >= cutoff
__global__ void collect_kernel(const float* __restrict__ cls) {
    const int b = blockIdx.y;
    const unsigned int cut = (unsigned int)g_cut[b];
    const float4* p = (const float4*)(cls + (size_t)b * NPB);
    const int n4 = NPB / 4;
    const int stride = gridDim.x * blockDim.x;

    for (int i = blockIdx.x * blockDim.x + threadIdx.x; i < n4; i += stride) {
        float4 v = p[i];
        unsigned int ks[4] = { f2key(v.x), f2key(v.y), f2key(v.z), f2key(v.w) };
        #pragma unroll
        for (int j = 0; j < 4; j++) {
            if ((ks[j] >> 21) >= cut) {
                int pos = atomicAdd(&g_cnt[b], 1);
                if (pos < CAP)
                    g_cand[b][pos] = make_uint2(ks[j], (unsigned int)(4 * i + j));
            }
        }
    }
}

// ---------------------------------------------------------------------------
// Pass 4: exact rank among candidates (key desc, index asc tie-break = jax
// top_k semantics), gather boxes, write [B, K, 6] output.
__global__ void select_kernel(const float* __restrict__ loc,
                              float* __restrict__ out) {
    __shared__ uint2 cand[CAP];
    const int b = blockIdx.x;
    const int n = min(g_cnt[b], CAP);
    for (int i = threadIdx.x; i < n; i += blockDim.x) cand[i] = g_cand[b][i];
    __syncthreads();

    for (int i = threadIdx.x; i < n; i += blockDim.x) {
        const unsigned int ki = cand[i].x;
        const unsigned int xi = cand[i].y;
        int rank = 0;
        for (int j = 0; j < n; j++) {
            unsigned int kj = cand[j].x;
            unsigned int xj = cand[j].y;
            rank += (kj > ki) || (kj == ki && xj < xi);
        }
        if (rank < KTOP) {
            unsigned int cls_id = xi % NCLS;
            unsigned int sp = xi / NCLS;
            float4 box = ((const float4*)(loc + (size_t)b * HW * 4))[sp];
            float* o = out + ((size_t)b * KTOP + rank) * 6;
            o[0] = box.x; o[1] = box.y; o[2] = box.z; o[3] = box.w;
            o[4] = key2f(ki);
            o[5] = (float)cls_id;
        }
    }
}

// ---------------------------------------------------------------------------
extern "C" void kernel_launch(void* const* d_in, const int* in_sizes, int n_in,
                              void* d_out, int out_size) {
    // cls_pred has 32*128*128*80 = 41943040 elems; loc_pred 32*128*128*4 = 2097152
    const float* cls = (const float*)d_in[0];
    const float* loc = (const float*)d_in[1];
    if (n_in >= 2 && in_sizes[0] < in_sizes[1]) {
        cls = (const float*)d_in[1];
        loc = (const float*)d_in[0];
    }
    float* out = (float*)d_out;

    zero_kernel<<<64, 256>>>();
    hist_kernel<<<dim3(128, BATCH), 256>>>(cls);
    cut_kernel<<<BATCH, CUT_THREADS>>>();
    collect_kernel<<<dim3(128, BATCH), 256>>>(cls);
    select_kernel<<<BATCH, 256>>>(loc, out);
}